// round 11
// baseline (speedup 1.0000x reference)
#include <cuda_runtime.h>
#include <cuda_fp16.h>
#include <math.h>
#include <stdint.h>

#define NNODE 50000
#define NEDGE 800000
#define ND    128
#define NH    8
#define DKK   16
#define FFD   512

// ---------------- scratch ----------------
__device__ float g_q [NNODE * ND];
__device__ float g_t1[NNODE * ND];
__device__ float g_x1[NNODE * ND];

// fp16 operand twins
__device__ __align__(16) __half g_hx [NNODE * ND];    // layer input (rewritten by ff2)
__device__ __align__(16) __half g_hk [NNODE * ND];    // k (fp16, gather path)
__device__ __align__(16) __half g_hv [NNODE * ND];    // v (fp16, gather path)
__device__ __align__(16) __half g_hwv[NNODE * ND];    // agg output
__device__ __align__(16) __half g_ht1[NNODE * ND];    // post-LN1
__device__ __align__(16) __half g_hff[NNODE * FFD];   // relu(ff1)
__device__ __align__(16) __half g_hWq[2 * ND * ND];
__device__ __align__(16) __half g_hWk[2 * ND * ND];
__device__ __align__(16) __half g_hWv[2 * ND * ND];
__device__ __align__(16) __half g_hWo[2 * ND * ND];
__device__ __align__(16) __half g_hW1[2 * FFD * ND];
__device__ __align__(16) __half g_hW2[2 * ND * FFD];

// CSR scratch
__device__ int  g_deg[NNODE];
__device__ int  g_off[NNODE + 1];
__device__ int2 g_pe [NEDGE];

// ---------------- helpers ----------------
__device__ __forceinline__ void mma_f16(float* c, const uint32_t* a, const uint32_t* b) {
    asm volatile(
        "mma.sync.aligned.m16n8k16.row.col.f32.f16.f16.f32 "
        "{%0,%1,%2,%3}, {%4,%5,%6,%7}, {%8,%9}, {%0,%1,%2,%3};"
        : "+f"(c[0]), "+f"(c[1]), "+f"(c[2]), "+f"(c[3])
        : "r"(a[0]), "r"(a[1]), "r"(a[2]), "r"(a[3]),
          "r"(b[0]), "r"(b[1]));
}

__device__ __forceinline__ void cp16h(void* dst, const __half* src, bool pred) {
    uint32_t d = (uint32_t)__cvta_generic_to_shared(dst);
    int sz = pred ? 16 : 0;
    asm volatile("cp.async.cg.shared.global [%0], [%1], 16, %2;"
                 :: "r"(d), "l"(src), "r"(sz));
}

// fp32 -> fp16 conversion (4 elems/thread; n % 4 == 0)
__global__ void cvt_kernel(const float* __restrict__ s, __half* __restrict__ d, int n)
{
    int i = (blockIdx.x * blockDim.x + threadIdx.x) * 4;
    if (i >= n) return;
    float4 f = *(const float4*)&s[i];
    *(__half2*)&d[i]     = __floats2half2_rn(f.x, f.y);
    *(__half2*)&d[i + 2] = __floats2half2_rn(f.z, f.w);
}

// ---------------- FP16 GEMM core (unchanged from R10) ----------------
#define KC 64
#define SK 36
#define SN 132
#define TILE_U32 (128 * SK)
#define NSTAGE 3
#define GEMM_SMEM_BYTES (NSTAGE * 2 * TILE_U32 * 4)   // 110592

template<bool RELU, bool LN>
__device__ __forceinline__ void gemm_body(
    const __half* __restrict__ X, const __half* __restrict__ W,
    const float* bias, const float* res,
    const float* gam, const float* bet,
    float* C, __half* Ch, int M, int K, int NOUT, int bm, int bn)
{
    extern __shared__ uint32_t smem[];

    const int tid  = threadIdx.x;
    const int lane = tid & 31;
    const int wid  = tid >> 5;
    const int g    = lane >> 2;
    const int tig  = lane & 3;
    const int wn   = (wid & 3) * 32;
    const int wm   = (wid >> 2) * 64;

    float c[2][8][4];
#pragma unroll
    for (int i = 0; i < 2; i++)
#pragma unroll
        for (int j = 0; j < 8; j++)
#pragma unroll
            for (int t = 0; t < 4; t++) c[i][j][t] = 0.f;

    const int nsteps = K / KC;

    auto prefetch = [&](int s, int b) {
        uint32_t* Wb = smem + b * 2 * TILE_U32;
        uint32_t* Xb = Wb + TILE_U32;
        int k0 = s * KC;
#pragma unroll
        for (int i = 0; i < 4; i++) {
            int idx = tid + i * 256;
            int r = idx >> 3, j = idx & 7;
            cp16h((char*)(Wb + r * SK) + j * 16, &W[(long)(bn + r) * K + k0 + j * 8], true);
        }
#pragma unroll
        for (int i = 0; i < 4; i++) {
            int idx = tid + i * 256;
            int r = idx >> 3, j = idx & 7;
            int gm = bm + r;
            cp16h((char*)(Xb + r * SK) + j * 16, &X[(long)gm * K + k0 + j * 8], gm < M);
        }
        asm volatile("cp.async.commit_group;" ::: "memory");
    };

    prefetch(0, 0);
    prefetch(1, 1);

    int buf = 0;
    for (int s = 0; s < nsteps; s++) {
        if (s + 1 < nsteps) asm volatile("cp.async.wait_group 1;" ::: "memory");
        else                asm volatile("cp.async.wait_group 0;" ::: "memory");
        __syncthreads();
        if (s + 2 < nsteps) {
            int nb = buf + 2; if (nb >= NSTAGE) nb -= NSTAGE;
            prefetch(s + 2, nb);
        }

        const uint32_t* Wsu = smem + buf * 2 * TILE_U32;
        const uint32_t* Xsu = Wsu + TILE_U32;

#pragma unroll
        for (int ks = 0; ks < 4; ks++) {
            const int kk = ks * 8;
            uint32_t a[2][4];
#pragma unroll
            for (int tn = 0; tn < 2; tn++) {
                int row = wn + tn * 16 + g;
                a[tn][0] = Wsu[row * SK + kk + tig];
                a[tn][1] = Wsu[(row + 8) * SK + kk + tig];
                a[tn][2] = Wsu[row * SK + kk + tig + 4];
                a[tn][3] = Wsu[(row + 8) * SK + kk + tig + 4];
            }
            uint32_t b[8][2];
#pragma unroll
            for (int tm = 0; tm < 8; tm++) {
                int col = wm + tm * 8 + g;
                b[tm][0] = Xsu[col * SK + kk + tig];
                b[tm][1] = Xsu[col * SK + kk + tig + 4];
            }
#pragma unroll
            for (int tn = 0; tn < 2; tn++)
#pragma unroll
                for (int tm = 0; tm < 8; tm++)
                    mma_f16(c[tn][tm], a[tn], b[tm]);
        }
        if (++buf == NSTAGE) buf = 0;
    }
    __syncthreads();

    float* Cs = (float*)smem;
#pragma unroll
    for (int tn = 0; tn < 2; tn++)
#pragma unroll
        for (int tm = 0; tm < 8; tm++) {
            int n = wn + tn * 16 + g;
            int m = wm + tm * 8 + tig * 2;
            Cs[m * SN + n]           = c[tn][tm][0];
            Cs[(m + 1) * SN + n]     = c[tn][tm][1];
            Cs[m * SN + n + 8]       = c[tn][tm][2];
            Cs[(m + 1) * SN + n + 8] = c[tn][tm][3];
        }
    __syncthreads();

#pragma unroll
    for (int i = 0; i < 16; i++) {
        int idx = tid + i * 256;
        int mm = idx >> 5, nq = idx & 31;
        int gm = bm + mm;
        if (gm >= M) continue;
        float4 cv = *(float4*)&Cs[mm * SN + nq * 4];
        if (bias) {
            float4 b4 = *(const float4*)&bias[bn + nq * 4];
            cv.x += b4.x; cv.y += b4.y; cv.z += b4.z; cv.w += b4.w;
        }
        if (res) {
            float4 r4 = *(const float4*)&res[(long)gm * NOUT + bn + nq * 4];
            cv.x += r4.x; cv.y += r4.y; cv.z += r4.z; cv.w += r4.w;
        }
        if (RELU) {
            cv.x = fmaxf(cv.x, 0.f); cv.y = fmaxf(cv.y, 0.f);
            cv.z = fmaxf(cv.z, 0.f); cv.w = fmaxf(cv.w, 0.f);
        }
        if (LN) {
            float s4 = cv.x + cv.y + cv.z + cv.w;
#pragma unroll
            for (int o = 16; o; o >>= 1) s4 += __shfl_xor_sync(0xffffffffu, s4, o);
            float mean = s4 * (1.f / 128.f);
            float dx = cv.x - mean, dy = cv.y - mean, dz = cv.z - mean, dw = cv.w - mean;
            float vv = dx * dx + dy * dy + dz * dz + dw * dw;
#pragma unroll
            for (int o = 16; o; o >>= 1) vv += __shfl_xor_sync(0xffffffffu, vv, o);
            float inv = rsqrtf(vv * (1.f / 128.f) + 1e-5f);
            float4 g4 = *(const float4*)&gam[nq * 4];
            float4 b4 = *(const float4*)&bet[nq * 4];
            cv.x = dx * inv * g4.x + b4.x;
            cv.y = dy * inv * g4.y + b4.y;
            cv.z = dz * inv * g4.z + b4.z;
            cv.w = dw * inv * g4.w + b4.w;
        }
        if (C) *(float4*)&C[(long)gm * NOUT + bn + nq * 4] = cv;
        if (Ch) {
            __half2* hp = (__half2*)&Ch[(long)gm * NOUT + bn + nq * 4];
            hp[0] = __floats2half2_rn(cv.x, cv.y);
            hp[1] = __floats2half2_rn(cv.z, cv.w);
        }
    }
}

template<bool RELU, bool LN>
__global__ __launch_bounds__(256, 2) void gemm_k(
    const __half* __restrict__ X, const __half* __restrict__ W,
    const float* bias, const float* res,
    const float* gam, const float* bet,
    float* C, __half* Ch, int M, int K, int NOUT)
{
    gemm_body<RELU, LN>(X, W, bias, res, gam, bet, C, Ch, M, K, NOUT,
                        blockIdx.x * 128, blockIdx.y * 128);
}

// fused q/k/v: blockIdx.y selects projection. q -> fp32, k/v -> fp16.
__global__ __launch_bounds__(256, 2) void qkv_k(
    const __half* __restrict__ X,
    const __half* __restrict__ Wq, const __half* __restrict__ Wk,
    const __half* __restrict__ Wv, const float* __restrict__ bq,
    float* __restrict__ q, __half* __restrict__ hk, __half* __restrict__ hv, int M)
{
    int w = blockIdx.y;
    const __half* W = (w == 0) ? Wq : (w == 1) ? Wk : Wv;
    const float* bias = (w == 0) ? bq : nullptr;
    float*  C  = (w == 0) ? q : nullptr;
    __half* Ch = (w == 1) ? hk : (w == 2) ? hv : nullptr;
    gemm_body<false, false>(X, W, bias, nullptr, nullptr, nullptr, C, Ch,
                            M, ND, ND, blockIdx.x * 128, 0);
}

// ================= CSR build =================
__global__ void hist_kernel(const int* __restrict__ dst)
{
    int e = blockIdx.x * blockDim.x + threadIdx.x;
    if (e < NEDGE) atomicAdd(&g_deg[dst[e]], 1);
}

__global__ void scan_kernel()
{
    __shared__ int sh[1024];
    __shared__ int carry;
    int t = threadIdx.x;
    if (t == 0) { carry = 0; g_off[0] = 0; }
    __syncthreads();
    for (int base = 0; base < NNODE; base += 1024) {
        int i = base + t;
        int val = (i < NNODE) ? g_deg[i] : 0;
        sh[t] = val;
        __syncthreads();
#pragma unroll
        for (int o = 1; o < 1024; o <<= 1) {
            int add = (t >= o) ? sh[t - o] : 0;
            __syncthreads();
            sh[t] += add;
            __syncthreads();
        }
        int inc = sh[t] + carry;
        if (i < NNODE) g_off[i + 1] = inc;
        __syncthreads();
        if (t == 1023) carry = inc;
        __syncthreads();
    }
}

__global__ void scatter_kernel(const int* __restrict__ src,
                               const int* __restrict__ dst,
                               const int* __restrict__ edges)
{
    int e = blockIdx.x * blockDim.x + threadIdx.x;
    if (e >= NEDGE) return;
    int d = dst[e];
    int idx = atomicAdd(&g_deg[d], -1) - 1;
    g_pe[g_off[d] + idx] = make_int2(src[e], edges[e]);
}

// ================= per-dst aggregation: fp16 k/v gathers, rel in smem =================
__global__ __launch_bounds__(256) void agg_kernel(const float* __restrict__ rel)
{
    __shared__ float srel[128 * DKK];   // 8 KB: full rel_embed table
    for (int i = threadIdx.x; i < 128 * DKK; i += 256) srel[i] = rel[i];
    __syncthreads();

    int node = (blockIdx.x * blockDim.x + threadIdx.x) >> 5;
    int lane = threadIdx.x & 31;
    if (node >= NNODE) return;

    const int beg = g_off[node];
    const int end = g_off[node + 1];

    const float4 q4 = *(const float4*)&g_q[(long)node * ND + lane * 4];
    float4 acc = make_float4(0.f, 0.f, 0.f, 0.f);
    float zacc = 0.f;

    const int eoff = (lane & 3) * 4;

    int i = beg;
    for (; i + 2 <= end; i += 2) {
        int2 p0 = g_pe[i];
        int2 p1 = g_pe[i + 1];
        uint2 kr0 = *(const uint2*)&g_hk[(long)p0.x * ND + lane * 4];
        uint2 kr1 = *(const uint2*)&g_hk[(long)p1.x * ND + lane * 4];
        uint2 vr0 = *(const uint2*)&g_hv[(long)p0.x * ND + lane * 4];
        uint2 vr1 = *(const uint2*)&g_hv[(long)p1.x * ND + lane * 4];
        const float4 e0 = *(const float4*)&srel[p0.y * DKK + eoff];
        const float4 e1 = *(const float4*)&srel[p1.y * DKK + eoff];

        float2 k0a = __half22float2(*(__half2*)&kr0.x);
        float2 k0b = __half22float2(*(__half2*)&kr0.y);
        float2 k1a = __half22float2(*(__half2*)&kr1.x);
        float2 k1b = __half22float2(*(__half2*)&kr1.y);

        float s0 = (k0a.x + e0.x) * q4.x + (k0a.y + e0.y) * q4.y +
                   (k0b.x + e0.z) * q4.z + (k0b.y + e0.w) * q4.w;
        float s1 = (k1a.x + e1.x) * q4.x + (k1a.y + e1.y) * q4.y +
                   (k1b.x + e1.z) * q4.z + (k1b.y + e1.w) * q4.w;
        s0 += __shfl_xor_sync(0xffffffffu, s0, 1);
        s1 += __shfl_xor_sync(0xffffffffu, s1, 1);
        s0 += __shfl_xor_sync(0xffffffffu, s0, 2);
        s1 += __shfl_xor_sync(0xffffffffu, s1, 2);

        float sc0 = __expf(fminf(fmaxf(s0 * 0.25f, -5.f), 5.f));
        float sc1 = __expf(fminf(fmaxf(s1 * 0.25f, -5.f), 5.f));

        float2 v0a = __half22float2(*(__half2*)&vr0.x);
        float2 v0b = __half22float2(*(__half2*)&vr0.y);
        float2 v1a = __half22float2(*(__half2*)&vr1.x);
        float2 v1b = __half22float2(*(__half2*)&vr1.y);

        acc.x += (v0a.x + e0.x) * sc0 + (v1a.x + e1.x) * sc1;
        acc.y += (v0a.y + e0.y) * sc0 + (v1a.y + e1.y) * sc1;
        acc.z += (v0b.x + e0.z) * sc0 + (v1b.x + e1.z) * sc1;
        acc.w += (v0b.y + e0.w) * sc0 + (v1b.y + e1.w) * sc1;
        zacc  += sc0 + sc1;
    }
    if (i < end) {
        int2 p0 = g_pe[i];
        uint2 kr0 = *(const uint2*)&g_hk[(long)p0.x * ND + lane * 4];
        uint2 vr0 = *(const uint2*)&g_hv[(long)p0.x * ND + lane * 4];
        const float4 e0 = *(const float4*)&srel[p0.y * DKK + eoff];
        float2 k0a = __half22float2(*(__half2*)&kr0.x);
        float2 k0b = __half22float2(*(__half2*)&kr0.y);
        float s0 = (k0a.x + e0.x) * q4.x + (k0a.y + e0.y) * q4.y +
                   (k0b.x + e0.z) * q4.z + (k0b.y + e0.w) * q4.w;
        s0 += __shfl_xor_sync(0xffffffffu, s0, 1);
        s0 += __shfl_xor_sync(0xffffffffu, s0, 2);
        float sc0 = __expf(fminf(fmaxf(s0 * 0.25f, -5.f), 5.f));
        float2 v0a = __half22float2(*(__half2*)&vr0.x);
        float2 v0b = __half22float2(*(__half2*)&vr0.y);
        acc.x += (v0a.x + e0.x) * sc0;
        acc.y += (v0a.y + e0.y) * sc0;
        acc.z += (v0b.x + e0.z) * sc0;
        acc.w += (v0b.y + e0.w) * sc0;
        zacc  += sc0;
    }

    float inv = 1.f / zacc;
    __half2* hp = (__half2*)&g_hwv[(long)node * ND + lane * 4];
    hp[0] = __floats2half2_rn(acc.x * inv, acc.y * inv);
    hp[1] = __floats2half2_rn(acc.z * inv, acc.w * inv);
}

// ---------------- host driver ----------------
extern "C" void kernel_launch(void* const* d_in, const int* in_sizes, int n_in,
                              void* d_out, int out_size)
{
    const float* x     = (const float*)d_in[0];
    const int*   edges = (const int*)  d_in[1];
    const int*   src   = (const int*)  d_in[2];
    const int*   dst   = (const int*)  d_in[3];
    const float* rel   = (const float*)d_in[4];
    const float* Wq    = (const float*)d_in[5];
    const float* bq    = (const float*)d_in[6];
    const float* Wk    = (const float*)d_in[7];
    const float* Wv    = (const float*)d_in[8];
    const float* Wo    = (const float*)d_in[9];
    const float* bo    = (const float*)d_in[10];
    const float* ln1g  = (const float*)d_in[11];
    const float* ln1b  = (const float*)d_in[12];
    const float* W1    = (const float*)d_in[13];
    const float* b1    = (const float*)d_in[14];
    const float* W2    = (const float*)d_in[15];
    const float* b2    = (const float*)d_in[16];
    const float* ln2g  = (const float*)d_in[17];
    const float* ln2b  = (const float*)d_in[18];

    const int M = NNODE;
    const int E = NEDGE;

    float *q, *t1, *x1;
    __half *hx, *hk, *hv, *hwv, *ht1, *hff, *hWq, *hWk, *hWv, *hWo, *hW1, *hW2;
    int* degp;
    cudaGetSymbolAddress((void**)&q,   g_q);
    cudaGetSymbolAddress((void**)&t1,  g_t1);
    cudaGetSymbolAddress((void**)&x1,  g_x1);
    cudaGetSymbolAddress((void**)&hx,  g_hx);
    cudaGetSymbolAddress((void**)&hk,  g_hk);
    cudaGetSymbolAddress((void**)&hv,  g_hv);
    cudaGetSymbolAddress((void**)&hwv, g_hwv);
    cudaGetSymbolAddress((void**)&ht1, g_ht1);
    cudaGetSymbolAddress((void**)&hff, g_hff);
    cudaGetSymbolAddress((void**)&hWq, g_hWq);
    cudaGetSymbolAddress((void**)&hWk, g_hWk);
    cudaGetSymbolAddress((void**)&hWv, g_hWv);
    cudaGetSymbolAddress((void**)&hWo, g_hWo);
    cudaGetSymbolAddress((void**)&hW1, g_hW1);
    cudaGetSymbolAddress((void**)&hW2, g_hW2);
    cudaGetSymbolAddress((void**)&degp, g_deg);

    cudaFuncSetAttribute(gemm_k<false, true>,
        cudaFuncAttributeMaxDynamicSharedMemorySize, GEMM_SMEM_BYTES);
    cudaFuncSetAttribute(gemm_k<true, false>,
        cudaFuncAttributeMaxDynamicSharedMemorySize, GEMM_SMEM_BYTES);
    cudaFuncSetAttribute(qkv_k,
        cudaFuncAttributeMaxDynamicSharedMemorySize, GEMM_SMEM_BYTES);

    const int MB = (M + 127) / 128;
    dim3 gQKV(MB, 3);
    dim3 gP(MB, 1);
    dim3 gF1(MB, FFD / 128);
    int eBlocks   = (E + 255) / 256;
    int aggBlocks = (M * 32 + 255) / 256;

    auto cvtLaunch = [](const float* s, __half* d, int n) {
        cvt_kernel<<<(n / 4 + 255) / 256, 256>>>(s, d, n);
    };

    // ---- one-time conversions ----
    cvtLaunch(x,  hx,  M * ND);
    cvtLaunch(Wq, hWq, 2 * ND * ND);
    cvtLaunch(Wk, hWk, 2 * ND * ND);
    cvtLaunch(Wv, hWv, 2 * ND * ND);
    cvtLaunch(Wo, hWo, 2 * ND * ND);
    cvtLaunch(W1, hW1, 2 * FFD * ND);
    cvtLaunch(W2, hW2, 2 * ND * FFD);

    // ---- CSR build ----
    cudaMemsetAsync(degp, 0, NNODE * sizeof(int));
    hist_kernel<<<eBlocks, 256>>>(dst);
    scan_kernel<<<1, 1024>>>();
    scatter_kernel<<<eBlocks, 256>>>(src, dst, edges);

    const float* xin = x;     // fp32 residual source
    for (int li = 0; li < 2; li++) {
        float* xout = (li == 0) ? x1 : (float*)d_out;
        const __half* wWq = hWq + (long)li * ND * ND;
        const __half* wWk = hWk + (long)li * ND * ND;
        const __half* wWv = hWv + (long)li * ND * ND;
        const __half* wWo = hWo + (long)li * ND * ND;
        const __half* wW1 = hW1 + (long)li * FFD * ND;
        const __half* wW2 = hW2 + (long)li * ND * FFD;

        // q/k/v projections: q fp32, k/v fp16
        qkv_k<<<gQKV, 256, GEMM_SMEM_BYTES>>>(hx, wWq, wWk, wWv, bq + li * ND, q, hk, hv, M);

        // attention aggregation -> hwv (fp16)
        agg_kernel<<<aggBlocks, 256>>>(rel);

        // o-proj + residual + LN1 -> t1 (fp32) + ht1 (fp16)
        gemm_k<false, true><<<gP, 256, GEMM_SMEM_BYTES>>>(
            hwv, wWo, bo + li * ND, xin, ln1g + li * ND, ln1b + li * ND,
            t1, ht1, M, ND, ND);

        // FF1: relu(ht1 @ W1^T + b1) -> hff (fp16 only)
        gemm_k<true, false><<<gF1, 256, GEMM_SMEM_BYTES>>>(
            ht1, wW1, b1 + li * FFD, nullptr, nullptr, nullptr,
            nullptr, hff, M, ND, FFD);

        // FF2 + residual(t1) + LN2 -> xout (fp32) + hx (fp16, next layer input)
        gemm_k<false, true><<<gP, 256, GEMM_SMEM_BYTES>>>(
            hff, wW2, b2 + li * ND, t1, ln2g + li * ND, ln2b + li * ND,
            xout, hx, M, FFD, ND);

        xin = xout;
    }
}

// round 12
// speedup vs baseline: 1.0632x; 1.0632x over previous
#include <cuda_runtime.h>
#include <cuda_fp16.h>
#include <math.h>
#include <stdint.h>

#define NNODE 50000
#define NEDGE 800000
#define ND    128
#define NH    8
#define DKK   16
#define FFD   512

// ---------------- scratch ----------------
__device__ float g_q [NNODE * ND];
__device__ float g_t1[NNODE * ND];
__device__ float g_x1[NNODE * ND];

// fp16 operand twins
__device__ __align__(16) __half g_hx [NNODE * ND];
__device__ __align__(16) __half g_hk [NNODE * ND];
__device__ __align__(16) __half g_hv [NNODE * ND];
__device__ __align__(16) __half g_hwv[NNODE * ND];
__device__ __align__(16) __half g_ht1[NNODE * ND];
__device__ __align__(16) __half g_hff[NNODE * FFD];
__device__ __align__(16) __half g_hWq[2 * ND * ND];
__device__ __align__(16) __half g_hWk[2 * ND * ND];
__device__ __align__(16) __half g_hWv[2 * ND * ND];
__device__ __align__(16) __half g_hWo[2 * ND * ND];
__device__ __align__(16) __half g_hW1[2 * FFD * ND];
__device__ __align__(16) __half g_hW2[2 * ND * FFD];

// CSR scratch
__device__ int  g_deg[NNODE];
__device__ int  g_off[NNODE + 1];
__device__ int2 g_pe [NEDGE];

// ---------------- helpers ----------------
__device__ __forceinline__ void mma_f16(float* c, const uint32_t* a, const uint32_t* b) {
    asm volatile(
        "mma.sync.aligned.m16n8k16.row.col.f32.f16.f16.f32 "
        "{%0,%1,%2,%3}, {%4,%5,%6,%7}, {%8,%9}, {%0,%1,%2,%3};"
        : "+f"(c[0]), "+f"(c[1]), "+f"(c[2]), "+f"(c[3])
        : "r"(a[0]), "r"(a[1]), "r"(a[2]), "r"(a[3]),
          "r"(b[0]), "r"(b[1]));
}

__device__ __forceinline__ void cp16h(void* dst, const __half* src, bool pred) {
    uint32_t d = (uint32_t)__cvta_generic_to_shared(dst);
    int sz = pred ? 16 : 0;
    asm volatile("cp.async.cg.shared.global [%0], [%1], 16, %2;"
                 :: "r"(d), "l"(src), "r"(sz));
}

__device__ __forceinline__ void cvt4(const float* s, __half* d) {
    float4 f = *(const float4*)s;
    *(__half2*)&d[0] = __floats2half2_rn(f.x, f.y);
    *(__half2*)&d[2] = __floats2half2_rn(f.z, f.w);
}

// single fused fp32->fp16 conversion: x + all 6 weight groups
#define NW_SMALL (2 * ND * ND)     // 32768
#define NW_BIG   (2 * ND * FFD)    // 131072
#define NX       (NNODE * ND)      // 6.4M
#define CVT_TOT  (NX + 4 * NW_SMALL + 2 * NW_BIG)

__global__ void cvt_all_kernel(
    const float* __restrict__ x,
    const float* __restrict__ Wq, const float* __restrict__ Wk,
    const float* __restrict__ Wv, const float* __restrict__ Wo,
    const float* __restrict__ W1, const float* __restrict__ W2)
{
    long i = (long)(blockIdx.x * blockDim.x + threadIdx.x) * 4;
    if (i >= CVT_TOT) return;
    if (i < NX) { cvt4(&x[i], &g_hx[i]); return; }
    long j = i - NX;
    if (j < NW_SMALL)            { cvt4(&Wq[j], &g_hWq[j]); return; }
    j -= NW_SMALL;
    if (j < NW_SMALL)            { cvt4(&Wk[j], &g_hWk[j]); return; }
    j -= NW_SMALL;
    if (j < NW_SMALL)            { cvt4(&Wv[j], &g_hWv[j]); return; }
    j -= NW_SMALL;
    if (j < NW_SMALL)            { cvt4(&Wo[j], &g_hWo[j]); return; }
    j -= NW_SMALL;
    if (j < NW_BIG)              { cvt4(&W1[j], &g_hW1[j]); return; }
    j -= NW_BIG;
    cvt4(&W2[j], &g_hW2[j]);
}

// ---------------- FP16 GEMM core (unchanged) ----------------
#define KC 64
#define SK 36
#define SN 132
#define TILE_U32 (128 * SK)
#define NSTAGE 3
#define GEMM_SMEM_BYTES (NSTAGE * 2 * TILE_U32 * 4)   // 110592

template<bool RELU, bool LN>
__device__ __forceinline__ void gemm_body(
    const __half* __restrict__ X, const __half* __restrict__ W,
    const float* bias, const float* res,
    const float* gam, const float* bet,
    float* C, __half* Ch, int M, int K, int NOUT, int bm, int bn)
{
    extern __shared__ uint32_t smem[];

    const int tid  = threadIdx.x;
    const int lane = tid & 31;
    const int wid  = tid >> 5;
    const int g    = lane >> 2;
    const int tig  = lane & 3;
    const int wn   = (wid & 3) * 32;
    const int wm   = (wid >> 2) * 64;

    float c[2][8][4];
#pragma unroll
    for (int i = 0; i < 2; i++)
#pragma unroll
        for (int j = 0; j < 8; j++)
#pragma unroll
            for (int t = 0; t < 4; t++) c[i][j][t] = 0.f;

    const int nsteps = K / KC;

    auto prefetch = [&](int s, int b) {
        uint32_t* Wb = smem + b * 2 * TILE_U32;
        uint32_t* Xb = Wb + TILE_U32;
        int k0 = s * KC;
#pragma unroll
        for (int i = 0; i < 4; i++) {
            int idx = tid + i * 256;
            int r = idx >> 3, j = idx & 7;
            cp16h((char*)(Wb + r * SK) + j * 16, &W[(long)(bn + r) * K + k0 + j * 8], true);
        }
#pragma unroll
        for (int i = 0; i < 4; i++) {
            int idx = tid + i * 256;
            int r = idx >> 3, j = idx & 7;
            int gm = bm + r;
            cp16h((char*)(Xb + r * SK) + j * 16, &X[(long)gm * K + k0 + j * 8], gm < M);
        }
        asm volatile("cp.async.commit_group;" ::: "memory");
    };

    prefetch(0, 0);
    prefetch(1, 1);

    int buf = 0;
    for (int s = 0; s < nsteps; s++) {
        if (s + 1 < nsteps) asm volatile("cp.async.wait_group 1;" ::: "memory");
        else                asm volatile("cp.async.wait_group 0;" ::: "memory");
        __syncthreads();
        if (s + 2 < nsteps) {
            int nb = buf + 2; if (nb >= NSTAGE) nb -= NSTAGE;
            prefetch(s + 2, nb);
        }

        const uint32_t* Wsu = smem + buf * 2 * TILE_U32;
        const uint32_t* Xsu = Wsu + TILE_U32;

#pragma unroll
        for (int ks = 0; ks < 4; ks++) {
            const int kk = ks * 8;
            uint32_t a[2][4];
#pragma unroll
            for (int tn = 0; tn < 2; tn++) {
                int row = wn + tn * 16 + g;
                a[tn][0] = Wsu[row * SK + kk + tig];
                a[tn][1] = Wsu[(row + 8) * SK + kk + tig];
                a[tn][2] = Wsu[row * SK + kk + tig + 4];
                a[tn][3] = Wsu[(row + 8) * SK + kk + tig + 4];
            }
            uint32_t b[8][2];
#pragma unroll
            for (int tm = 0; tm < 8; tm++) {
                int col = wm + tm * 8 + g;
                b[tm][0] = Xsu[col * SK + kk + tig];
                b[tm][1] = Xsu[col * SK + kk + tig + 4];
            }
#pragma unroll
            for (int tn = 0; tn < 2; tn++)
#pragma unroll
                for (int tm = 0; tm < 8; tm++)
                    mma_f16(c[tn][tm], a[tn], b[tm]);
        }
        if (++buf == NSTAGE) buf = 0;
    }
    __syncthreads();

    float* Cs = (float*)smem;
#pragma unroll
    for (int tn = 0; tn < 2; tn++)
#pragma unroll
        for (int tm = 0; tm < 8; tm++) {
            int n = wn + tn * 16 + g;
            int m = wm + tm * 8 + tig * 2;
            Cs[m * SN + n]           = c[tn][tm][0];
            Cs[(m + 1) * SN + n]     = c[tn][tm][1];
            Cs[m * SN + n + 8]       = c[tn][tm][2];
            Cs[(m + 1) * SN + n + 8] = c[tn][tm][3];
        }
    __syncthreads();

#pragma unroll
    for (int i = 0; i < 16; i++) {
        int idx = tid + i * 256;
        int mm = idx >> 5, nq = idx & 31;
        int gm = bm + mm;
        if (gm >= M) continue;
        float4 cv = *(float4*)&Cs[mm * SN + nq * 4];
        if (bias) {
            float4 b4 = *(const float4*)&bias[bn + nq * 4];
            cv.x += b4.x; cv.y += b4.y; cv.z += b4.z; cv.w += b4.w;
        }
        if (res) {
            float4 r4 = *(const float4*)&res[(long)gm * NOUT + bn + nq * 4];
            cv.x += r4.x; cv.y += r4.y; cv.z += r4.z; cv.w += r4.w;
        }
        if (RELU) {
            cv.x = fmaxf(cv.x, 0.f); cv.y = fmaxf(cv.y, 0.f);
            cv.z = fmaxf(cv.z, 0.f); cv.w = fmaxf(cv.w, 0.f);
        }
        if (LN) {
            float s4 = cv.x + cv.y + cv.z + cv.w;
#pragma unroll
            for (int o = 16; o; o >>= 1) s4 += __shfl_xor_sync(0xffffffffu, s4, o);
            float mean = s4 * (1.f / 128.f);
            float dx = cv.x - mean, dy = cv.y - mean, dz = cv.z - mean, dw = cv.w - mean;
            float vv = dx * dx + dy * dy + dz * dz + dw * dw;
#pragma unroll
            for (int o = 16; o; o >>= 1) vv += __shfl_xor_sync(0xffffffffu, vv, o);
            float inv = rsqrtf(vv * (1.f / 128.f) + 1e-5f);
            float4 g4 = *(const float4*)&gam[nq * 4];
            float4 b4 = *(const float4*)&bet[nq * 4];
            cv.x = dx * inv * g4.x + b4.x;
            cv.y = dy * inv * g4.y + b4.y;
            cv.z = dz * inv * g4.z + b4.z;
            cv.w = dw * inv * g4.w + b4.w;
        }
        if (C) *(float4*)&C[(long)gm * NOUT + bn + nq * 4] = cv;
        if (Ch) {
            __half2* hp = (__half2*)&Ch[(long)gm * NOUT + bn + nq * 4];
            hp[0] = __floats2half2_rn(cv.x, cv.y);
            hp[1] = __floats2half2_rn(cv.z, cv.w);
        }
    }
}

template<bool RELU, bool LN>
__global__ __launch_bounds__(256, 2) void gemm_k(
    const __half* __restrict__ X, const __half* __restrict__ W,
    const float* bias, const float* res,
    const float* gam, const float* bet,
    float* C, __half* Ch, int M, int K, int NOUT)
{
    gemm_body<RELU, LN>(X, W, bias, res, gam, bet, C, Ch, M, K, NOUT,
                        blockIdx.x * 128, blockIdx.y * 128);
}

__global__ __launch_bounds__(256, 2) void qkv_k(
    const __half* __restrict__ X,
    const __half* __restrict__ Wq, const __half* __restrict__ Wk,
    const __half* __restrict__ Wv, const float* __restrict__ bq,
    float* __restrict__ q, __half* __restrict__ hk, __half* __restrict__ hv, int M)
{
    int w = blockIdx.y;
    const __half* W = (w == 0) ? Wq : (w == 1) ? Wk : Wv;
    const float* bias = (w == 0) ? bq : nullptr;
    float*  C  = (w == 0) ? q : nullptr;
    __half* Ch = (w == 1) ? hk : (w == 2) ? hv : nullptr;
    gemm_body<false, false>(X, W, bias, nullptr, nullptr, nullptr, C, Ch,
                            M, ND, ND, blockIdx.x * 128, 0);
}

// ================= CSR build =================
__global__ void hist_kernel(const int* __restrict__ dst)
{
    int e = blockIdx.x * blockDim.x + threadIdx.x;
    if (e < NEDGE) atomicAdd(&g_deg[dst[e]], 1);
}

// fast single-block scan: serial per-thread chunks + one warp-shuffle block scan
__global__ __launch_bounds__(1024) void scan_kernel()
{
    __shared__ int warpsum[32];
    const int CH = (NNODE + 1023) / 1024;   // 49
    int t = threadIdx.x;
    int base = t * CH;

    int s = 0;
    for (int i = 0; i < CH; i++) {
        int idx = base + i;
        if (idx < NNODE) s += g_deg[idx];
    }
    int lane = t & 31, wid = t >> 5;
    int v = s;
#pragma unroll
    for (int o = 1; o < 32; o <<= 1) {
        int n = __shfl_up_sync(0xffffffffu, v, o);
        if (lane >= o) v += n;
    }
    if (lane == 31) warpsum[wid] = v;
    __syncthreads();
    if (wid == 0) {
        int w = warpsum[lane];
#pragma unroll
        for (int o = 1; o < 32; o <<= 1) {
            int n = __shfl_up_sync(0xffffffffu, w, o);
            if (lane >= o) w += n;
        }
        warpsum[lane] = w;
    }
    __syncthreads();
    int run = v - s + (wid ? warpsum[wid - 1] : 0);   // exclusive prefix
    if (t == 0) g_off[0] = 0;
    for (int i = 0; i < CH; i++) {
        int idx = base + i;
        if (idx < NNODE) { run += g_deg[idx]; g_off[idx + 1] = run; }
    }
}

__global__ void scatter_kernel(const int* __restrict__ src,
                               const int* __restrict__ dst,
                               const int* __restrict__ edges)
{
    int e = blockIdx.x * blockDim.x + threadIdx.x;
    if (e >= NEDGE) return;
    int d = dst[e];
    int idx = atomicAdd(&g_deg[d], -1) - 1;
    g_pe[g_off[d] + idx] = make_int2(src[e], edges[e]);
}

// ================= per-dst aggregation (fp16 gathers, rel in smem) =================
__global__ __launch_bounds__(256) void agg_kernel(const float* __restrict__ rel)
{
    __shared__ float srel[128 * DKK];   // 8 KB
    for (int i = threadIdx.x; i < 128 * DKK; i += 256) srel[i] = rel[i];
    __syncthreads();

    int node = (blockIdx.x * blockDim.x + threadIdx.x) >> 5;
    int lane = threadIdx.x & 31;
    if (node >= NNODE) return;

    const int beg = g_off[node];
    const int end = g_off[node + 1];

    const float4 q4 = *(const float4*)&g_q[(long)node * ND + lane * 4];
    float4 acc = make_float4(0.f, 0.f, 0.f, 0.f);
    float zacc = 0.f;

    const int eoff = (lane & 3) * 4;

    int i = beg;
    for (; i + 2 <= end; i += 2) {
        int2 p0 = g_pe[i];
        int2 p1 = g_pe[i + 1];
        uint2 kr0 = *(const uint2*)&g_hk[(long)p0.x * ND + lane * 4];
        uint2 kr1 = *(const uint2*)&g_hk[(long)p1.x * ND + lane * 4];
        uint2 vr0 = *(const uint2*)&g_hv[(long)p0.x * ND + lane * 4];
        uint2 vr1 = *(const uint2*)&g_hv[(long)p1.x * ND + lane * 4];
        const float4 e0 = *(const float4*)&srel[p0.y * DKK + eoff];
        const float4 e1 = *(const float4*)&srel[p1.y * DKK + eoff];

        float2 k0a = __half22float2(*(__half2*)&kr0.x);
        float2 k0b = __half22float2(*(__half2*)&kr0.y);
        float2 k1a = __half22float2(*(__half2*)&kr1.x);
        float2 k1b = __half22float2(*(__half2*)&kr1.y);

        float s0 = (k0a.x + e0.x) * q4.x + (k0a.y + e0.y) * q4.y +
                   (k0b.x + e0.z) * q4.z + (k0b.y + e0.w) * q4.w;
        float s1 = (k1a.x + e1.x) * q4.x + (k1a.y + e1.y) * q4.y +
                   (k1b.x + e1.z) * q4.z + (k1b.y + e1.w) * q4.w;
        s0 += __shfl_xor_sync(0xffffffffu, s0, 1);
        s1 += __shfl_xor_sync(0xffffffffu, s1, 1);
        s0 += __shfl_xor_sync(0xffffffffu, s0, 2);
        s1 += __shfl_xor_sync(0xffffffffu, s1, 2);

        float sc0 = __expf(fminf(fmaxf(s0 * 0.25f, -5.f), 5.f));
        float sc1 = __expf(fminf(fmaxf(s1 * 0.25f, -5.f), 5.f));

        float2 v0a = __half22float2(*(__half2*)&vr0.x);
        float2 v0b = __half22float2(*(__half2*)&vr0.y);
        float2 v1a = __half22float2(*(__half2*)&vr1.x);
        float2 v1b = __half22float2(*(__half2*)&vr1.y);

        acc.x += (v0a.x + e0.x) * sc0 + (v1a.x + e1.x) * sc1;
        acc.y += (v0a.y + e0.y) * sc0 + (v1a.y + e1.y) * sc1;
        acc.z += (v0b.x + e0.z) * sc0 + (v1b.x + e1.z) * sc1;
        acc.w += (v0b.y + e0.w) * sc0 + (v1b.y + e1.w) * sc1;
        zacc  += sc0 + sc1;
    }
    if (i < end) {
        int2 p0 = g_pe[i];
        uint2 kr0 = *(const uint2*)&g_hk[(long)p0.x * ND + lane * 4];
        uint2 vr0 = *(const uint2*)&g_hv[(long)p0.x * ND + lane * 4];
        const float4 e0 = *(const float4*)&srel[p0.y * DKK + eoff];
        float2 k0a = __half22float2(*(__half2*)&kr0.x);
        float2 k0b = __half22float2(*(__half2*)&kr0.y);
        float s0 = (k0a.x + e0.x) * q4.x + (k0a.y + e0.y) * q4.y +
                   (k0b.x + e0.z) * q4.z + (k0b.y + e0.w) * q4.w;
        s0 += __shfl_xor_sync(0xffffffffu, s0, 1);
        s0 += __shfl_xor_sync(0xffffffffu, s0, 2);
        float sc0 = __expf(fminf(fmaxf(s0 * 0.25f, -5.f), 5.f));
        float2 v0a = __half22float2(*(__half2*)&vr0.x);
        float2 v0b = __half22float2(*(__half2*)&vr0.y);
        acc.x += (v0a.x + e0.x) * sc0;
        acc.y += (v0a.y + e0.y) * sc0;
        acc.z += (v0b.x + e0.z) * sc0;
        acc.w += (v0b.y + e0.w) * sc0;
        zacc  += sc0;
    }

    float inv = 1.f / zacc;
    __half2* hp = (__half2*)&g_hwv[(long)node * ND + lane * 4];
    hp[0] = __floats2half2_rn(acc.x * inv, acc.y * inv);
    hp[1] = __floats2half2_rn(acc.z * inv, acc.w * inv);
}

// ---------------- host driver ----------------
extern "C" void kernel_launch(void* const* d_in, const int* in_sizes, int n_in,
                              void* d_out, int out_size)
{
    const float* x     = (const float*)d_in[0];
    const int*   edges = (const int*)  d_in[1];
    const int*   src   = (const int*)  d_in[2];
    const int*   dst   = (const int*)  d_in[3];
    const float* rel   = (const float*)d_in[4];
    const float* Wq    = (const float*)d_in[5];
    const float* bq    = (const float*)d_in[6];
    const float* Wk    = (const float*)d_in[7];
    const float* Wv    = (const float*)d_in[8];
    const float* Wo    = (const float*)d_in[9];
    const float* bo    = (const float*)d_in[10];
    const float* ln1g  = (const float*)d_in[11];
    const float* ln1b  = (const float*)d_in[12];
    const float* W1    = (const float*)d_in[13];
    const float* b1    = (const float*)d_in[14];
    const float* W2    = (const float*)d_in[15];
    const float* b2    = (const float*)d_in[16];
    const float* ln2g  = (const float*)d_in[17];
    const float* ln2b  = (const float*)d_in[18];

    const int M = NNODE;
    const int E = NEDGE;

    float *q, *t1, *x1;
    __half *hx, *hk, *hv, *hwv, *ht1, *hff, *hWq, *hWk, *hWv, *hWo, *hW1, *hW2;
    int* degp;
    cudaGetSymbolAddress((void**)&q,   g_q);
    cudaGetSymbolAddress((void**)&t1,  g_t1);
    cudaGetSymbolAddress((void**)&x1,  g_x1);
    cudaGetSymbolAddress((void**)&hx,  g_hx);
    cudaGetSymbolAddress((void**)&hk,  g_hk);
    cudaGetSymbolAddress((void**)&hv,  g_hv);
    cudaGetSymbolAddress((void**)&hwv, g_hwv);
    cudaGetSymbolAddress((void**)&ht1, g_ht1);
    cudaGetSymbolAddress((void**)&hff, g_hff);
    cudaGetSymbolAddress((void**)&hWq, g_hWq);
    cudaGetSymbolAddress((void**)&hWk, g_hWk);
    cudaGetSymbolAddress((void**)&hWv, g_hWv);
    cudaGetSymbolAddress((void**)&hWo, g_hWo);
    cudaGetSymbolAddress((void**)&hW1, g_hW1);
    cudaGetSymbolAddress((void**)&hW2, g_hW2);
    cudaGetSymbolAddress((void**)&degp, g_deg);

    cudaFuncSetAttribute(gemm_k<false, true>,
        cudaFuncAttributeMaxDynamicSharedMemorySize, GEMM_SMEM_BYTES);
    cudaFuncSetAttribute(gemm_k<true, false>,
        cudaFuncAttributeMaxDynamicSharedMemorySize, GEMM_SMEM_BYTES);
    cudaFuncSetAttribute(qkv_k,
        cudaFuncAttributeMaxDynamicSharedMemorySize, GEMM_SMEM_BYTES);

    const int MB = (M + 127) / 128;
    dim3 gQKV(MB, 3);
    dim3 gP(MB, 1);
    dim3 gF1(MB, FFD / 128);
    int eBlocks   = (E + 255) / 256;
    int aggBlocks = (M * 32 + 255) / 256;

    // ---- one fused conversion launch ----
    cvt_all_kernel<<<(CVT_TOT / 4 + 255) / 256, 256>>>(x, Wq, Wk, Wv, Wo, W1, W2);

    // ---- CSR build ----
    cudaMemsetAsync(degp, 0, NNODE * sizeof(int));
    hist_kernel<<<eBlocks, 256>>>(dst);
    scan_kernel<<<1, 1024>>>();
    scatter_kernel<<<eBlocks, 256>>>(src, dst, edges);

    const float* xin = x;     // fp32 residual source
    for (int li = 0; li < 2; li++) {
        float* xout = (li == 0) ? x1 : (float*)d_out;
        const __half* wWq = hWq + (long)li * ND * ND;
        const __half* wWk = hWk + (long)li * ND * ND;
        const __half* wWv = hWv + (long)li * ND * ND;
        const __half* wWo = hWo + (long)li * ND * ND;
        const __half* wW1 = hW1 + (long)li * FFD * ND;
        const __half* wW2 = hW2 + (long)li * ND * FFD;

        qkv_k<<<gQKV, 256, GEMM_SMEM_BYTES>>>(hx, wWq, wWk, wWv, bq + li * ND, q, hk, hv, M);

        agg_kernel<<<aggBlocks, 256>>>(rel);

        gemm_k<false, true><<<gP, 256, GEMM_SMEM_BYTES>>>(
            hwv, wWo, bo + li * ND, xin, ln1g + li * ND, ln1b + li * ND,
            t1, ht1, M, ND, ND);

        gemm_k<true, false><<<gF1, 256, GEMM_SMEM_BYTES>>>(
            ht1, wW1, b1 + li * FFD, nullptr, nullptr, nullptr,
            nullptr, hff, M, ND, FFD);

        gemm_k<false, true><<<gP, 256, GEMM_SMEM_BYTES>>>(
            hff, wW2, b2 + li * ND, t1, ln2g + li * ND, ln2b + li * ND,
            xout, hx, M, FFD, ND);

        xin = xout;
    }
}

// round 14
// speedup vs baseline: 1.0757x; 1.0118x over previous
#include <cuda_runtime.h>
#include <cuda_fp16.h>
#include <math.h>
#include <stdint.h>

#define NNODE 50000
#define NEDGE 800000
#define ND    128
#define NH    8
#define DKK   16
#define FFD   512

// ---------------- scratch ----------------
__device__ float g_q [NNODE * ND];
__device__ float g_t1[NNODE * ND];
__device__ float g_x1[NNODE * ND];

// fp16 operand twins
__device__ __align__(16) __half g_hx [NNODE * ND];
__device__ __align__(16) __half g_hk [NNODE * ND];
__device__ __align__(16) __half g_hv [NNODE * ND];
__device__ __align__(16) __half g_hwv[NNODE * ND];
__device__ __align__(16) __half g_ht1[NNODE * ND];
__device__ __align__(16) __half g_hff[NNODE * FFD];
__device__ __align__(16) __half g_hWq[2 * ND * ND];
__device__ __align__(16) __half g_hWk[2 * ND * ND];
__device__ __align__(16) __half g_hWv[2 * ND * ND];
__device__ __align__(16) __half g_hWo[2 * ND * ND];
__device__ __align__(16) __half g_hW1[2 * FFD * ND];
__device__ __align__(16) __half g_hW2[2 * ND * FFD];

// CSR scratch
__device__ int  g_deg[NNODE];
__device__ int  g_off[NNODE + 1];
__device__ int2 g_pe [NEDGE];

// ---------------- helpers ----------------
__device__ __forceinline__ void mma_f16(float* c, const uint32_t* a, const uint32_t* b) {
    asm volatile(
        "mma.sync.aligned.m16n8k16.row.col.f32.f16.f16.f32 "
        "{%0,%1,%2,%3}, {%4,%5,%6,%7}, {%8,%9}, {%0,%1,%2,%3};"
        : "+f"(c[0]), "+f"(c[1]), "+f"(c[2]), "+f"(c[3])
        : "r"(a[0]), "r"(a[1]), "r"(a[2]), "r"(a[3]),
          "r"(b[0]), "r"(b[1]));
}

__device__ __forceinline__ void ldsm4(uint32_t& r0, uint32_t& r1, uint32_t& r2, uint32_t& r3,
                                      uint32_t addr) {
    asm volatile("ldmatrix.sync.aligned.m8n8.x4.shared.b16 {%0,%1,%2,%3}, [%4];"
                 : "=r"(r0), "=r"(r1), "=r"(r2), "=r"(r3) : "r"(addr));
}

__device__ __forceinline__ void cp16h(void* dst, const __half* src, bool pred) {
    uint32_t d = (uint32_t)__cvta_generic_to_shared(dst);
    int sz = pred ? 16 : 0;
    asm volatile("cp.async.cg.shared.global [%0], [%1], 16, %2;"
                 :: "r"(d), "l"(src), "r"(sz));
}

__device__ __forceinline__ void cvt4(const float* s, __half* d) {
    float4 f = *(const float4*)s;
    *(__half2*)&d[0] = __floats2half2_rn(f.x, f.y);
    *(__half2*)&d[2] = __floats2half2_rn(f.z, f.w);
}

// single fused fp32->fp16 conversion: x + all 6 weight groups
#define NW_SMALL (2 * ND * ND)     // 32768
#define NW_BIG   (2 * ND * FFD)    // 131072
#define NX       (NNODE * ND)      // 6.4M
#define CVT_TOT  (NX + 4 * NW_SMALL + 2 * NW_BIG)

__global__ void cvt_all_kernel(
    const float* __restrict__ x,
    const float* __restrict__ Wq, const float* __restrict__ Wk,
    const float* __restrict__ Wv, const float* __restrict__ Wo,
    const float* __restrict__ W1, const float* __restrict__ W2)
{
    long i = (long)(blockIdx.x * blockDim.x + threadIdx.x) * 4;
    if (i >= CVT_TOT) return;
    if (i < NX) { cvt4(&x[i], &g_hx[i]); return; }
    long j = i - NX;
    if (j < NW_SMALL)            { cvt4(&Wq[j], &g_hWq[j]); return; }
    j -= NW_SMALL;
    if (j < NW_SMALL)            { cvt4(&Wk[j], &g_hWk[j]); return; }
    j -= NW_SMALL;
    if (j < NW_SMALL)            { cvt4(&Wv[j], &g_hWv[j]); return; }
    j -= NW_SMALL;
    if (j < NW_SMALL)            { cvt4(&Wo[j], &g_hWo[j]); return; }
    j -= NW_SMALL;
    if (j < NW_BIG)              { cvt4(&W1[j], &g_hW1[j]); return; }
    j -= NW_BIG;
    cvt4(&W2[j], &g_hW2[j]);
}

// ---------------- FP16 GEMM core: ldmatrix fragment loads ----------------
#define KC 64
#define SK 36
#define SN 132
#define TILE_U32 (128 * SK)
#define NSTAGE 3
#define GEMM_SMEM_BYTES (NSTAGE * 2 * TILE_U32 * 4)   // 110592

template<bool RELU, bool LN>
__device__ __forceinline__ void gemm_body(
    const __half* __restrict__ X, const __half* __restrict__ W,
    const float* bias, const float* res,
    const float* gam, const float* bet,
    float* C, __half* Ch, int M, int K, int NOUT, int bm, int bn)
{
    extern __shared__ uint32_t smem[];

    const int tid  = threadIdx.x;
    const int lane = tid & 31;
    const int wid  = tid >> 5;
    const int g    = lane >> 2;
    const int tig  = lane & 3;
    const int wn   = (wid & 3) * 32;
    const int wm   = (wid >> 2) * 64;

    // ldmatrix per-lane byte offsets (relative to operand tile base)
    const int grp = lane >> 3, sub = lane & 7;
    uint32_t aoff[2], boff[4];
#pragma unroll
    for (int tn = 0; tn < 2; tn++)
        aoff[tn] = ((wn + tn * 16 + (grp & 1) * 8 + sub) * SK + (grp >> 1) * 4) * 4;
#pragma unroll
    for (int p = 0; p < 4; p++)
        boff[p] = ((wm + p * 16 + (grp >> 1) * 8 + sub) * SK + (grp & 1) * 4) * 4;

    const uint32_t sbase = (uint32_t)__cvta_generic_to_shared(smem);

    float c[2][8][4];
#pragma unroll
    for (int i = 0; i < 2; i++)
#pragma unroll
        for (int j = 0; j < 8; j++)
#pragma unroll
            for (int t = 0; t < 4; t++) c[i][j][t] = 0.f;

    const int nsteps = K / KC;

    auto prefetch = [&](int s, int b) {
        uint32_t* Wb = smem + b * 2 * TILE_U32;
        uint32_t* Xb = Wb + TILE_U32;
        int k0 = s * KC;
#pragma unroll
        for (int i = 0; i < 4; i++) {
            int idx = tid + i * 256;
            int r = idx >> 3, j = idx & 7;
            cp16h((char*)(Wb + r * SK) + j * 16, &W[(long)(bn + r) * K + k0 + j * 8], true);
        }
#pragma unroll
        for (int i = 0; i < 4; i++) {
            int idx = tid + i * 256;
            int r = idx >> 3, j = idx & 7;
            int gm = bm + r;
            cp16h((char*)(Xb + r * SK) + j * 16, &X[(long)gm * K + k0 + j * 8], gm < M);
        }
        asm volatile("cp.async.commit_group;" ::: "memory");
    };

    prefetch(0, 0);
    prefetch(1, 1);

    int buf = 0;
    for (int s = 0; s < nsteps; s++) {
        if (s + 1 < nsteps) asm volatile("cp.async.wait_group 1;" ::: "memory");
        else                asm volatile("cp.async.wait_group 0;" ::: "memory");
        __syncthreads();
        if (s + 2 < nsteps) {
            int nb = buf + 2; if (nb >= NSTAGE) nb -= NSTAGE;
            prefetch(s + 2, nb);
        }

        const uint32_t Wbase = sbase + buf * 2 * TILE_U32 * 4;
        const uint32_t Xbase = Wbase + TILE_U32 * 4;

#pragma unroll
        for (int ks = 0; ks < 4; ks++) {
            const uint32_t kkb = ks * 32;       // 8 u32 = 32 bytes per k16 step
            uint32_t a[2][4];
            ldsm4(a[0][0], a[0][1], a[0][2], a[0][3], Wbase + aoff[0] + kkb);
            ldsm4(a[1][0], a[1][1], a[1][2], a[1][3], Wbase + aoff[1] + kkb);
            uint32_t b[8][2];
            ldsm4(b[0][0], b[0][1], b[1][0], b[1][1], Xbase + boff[0] + kkb);
            ldsm4(b[2][0], b[2][1], b[3][0], b[3][1], Xbase + boff[1] + kkb);
            ldsm4(b[4][0], b[4][1], b[5][0], b[5][1], Xbase + boff[2] + kkb);
            ldsm4(b[6][0], b[6][1], b[7][0], b[7][1], Xbase + boff[3] + kkb);
#pragma unroll
            for (int tn = 0; tn < 2; tn++)
#pragma unroll
                for (int tm = 0; tm < 8; tm++)
                    mma_f16(c[tn][tm], a[tn], b[tm]);
        }
        if (++buf == NSTAGE) buf = 0;
    }
    __syncthreads();

    float* Cs = (float*)smem;
#pragma unroll
    for (int tn = 0; tn < 2; tn++)
#pragma unroll
        for (int tm = 0; tm < 8; tm++) {
            int n = wn + tn * 16 + g;
            int m = wm + tm * 8 + tig * 2;
            Cs[m * SN + n]           = c[tn][tm][0];
            Cs[(m + 1) * SN + n]     = c[tn][tm][1];
            Cs[m * SN + n + 8]       = c[tn][tm][2];
            Cs[(m + 1) * SN + n + 8] = c[tn][tm][3];
        }
    __syncthreads();

#pragma unroll
    for (int i = 0; i < 16; i++) {
        int idx = tid + i * 256;
        int mm = idx >> 5, nq = idx & 31;
        int gm = bm + mm;
        if (gm >= M) continue;
        float4 cv = *(float4*)&Cs[mm * SN + nq * 4];
        if (bias) {
            float4 b4 = *(const float4*)&bias[bn + nq * 4];
            cv.x += b4.x; cv.y += b4.y; cv.z += b4.z; cv.w += b4.w;
        }
        if (res) {
            float4 r4 = *(const float4*)&res[(long)gm * NOUT + bn + nq * 4];
            cv.x += r4.x; cv.y += r4.y; cv.z += r4.z; cv.w += r4.w;
        }
        if (RELU) {
            cv.x = fmaxf(cv.x, 0.f); cv.y = fmaxf(cv.y, 0.f);
            cv.z = fmaxf(cv.z, 0.f); cv.w = fmaxf(cv.w, 0.f);
        }
        if (LN) {
            float s4 = cv.x + cv.y + cv.z + cv.w;
#pragma unroll
            for (int o = 16; o; o >>= 1) s4 += __shfl_xor_sync(0xffffffffu, s4, o);
            float mean = s4 * (1.f / 128.f);
            float dx = cv.x - mean, dy = cv.y - mean, dz = cv.z - mean, dw = cv.w - mean;
            float vv = dx * dx + dy * dy + dz * dz + dw * dw;
#pragma unroll
            for (int o = 16; o; o >>= 1) vv += __shfl_xor_sync(0xffffffffu, vv, o);
            float inv = rsqrtf(vv * (1.f / 128.f) + 1e-5f);
            float4 g4 = *(const float4*)&gam[nq * 4];
            float4 b4 = *(const float4*)&bet[nq * 4];
            cv.x = dx * inv * g4.x + b4.x;
            cv.y = dy * inv * g4.y + b4.y;
            cv.z = dz * inv * g4.z + b4.z;
            cv.w = dw * inv * g4.w + b4.w;
        }
        if (C) *(float4*)&C[(long)gm * NOUT + bn + nq * 4] = cv;
        if (Ch) {
            __half2* hp = (__half2*)&Ch[(long)gm * NOUT + bn + nq * 4];
            hp[0] = __floats2half2_rn(cv.x, cv.y);
            hp[1] = __floats2half2_rn(cv.z, cv.w);
        }
    }
}

template<bool RELU, bool LN>
__global__ __launch_bounds__(256, 2) void gemm_k(
    const __half* __restrict__ X, const __half* __restrict__ W,
    const float* bias, const float* res,
    const float* gam, const float* bet,
    float* C, __half* Ch, int M, int K, int NOUT)
{
    gemm_body<RELU, LN>(X, W, bias, res, gam, bet, C, Ch, M, K, NOUT,
                        blockIdx.x * 128, blockIdx.y * 128);
}

__global__ __launch_bounds__(256, 2) void qkv_k(
    const __half* __restrict__ X,
    const __half* __restrict__ Wq, const __half* __restrict__ Wk,
    const __half* __restrict__ Wv, const float* __restrict__ bq,
    float* __restrict__ q, __half* __restrict__ hk, __half* __restrict__ hv, int M)
{
    int w = blockIdx.y;
    const __half* W = (w == 0) ? Wq : (w == 1) ? Wk : Wv;
    const float* bias = (w == 0) ? bq : nullptr;
    float*  C  = (w == 0) ? q : nullptr;
    __half* Ch = (w == 1) ? hk : (w == 2) ? hv : nullptr;
    gemm_body<false, false>(X, W, bias, nullptr, nullptr, nullptr, C, Ch,
                            M, ND, ND, blockIdx.x * 128, 0);
}

// ================= CSR build =================
__global__ void hist_kernel(const int* __restrict__ dst)
{
    int e = blockIdx.x * blockDim.x + threadIdx.x;
    if (e < NEDGE) atomicAdd(&g_deg[dst[e]], 1);
}

__global__ __launch_bounds__(1024) void scan_kernel()
{
    __shared__ int warpsum[32];
    const int CH = (NNODE + 1023) / 1024;   // 49
    int t = threadIdx.x;
    int base = t * CH;

    int s = 0;
    for (int i = 0; i < CH; i++) {
        int idx = base + i;
        if (idx < NNODE) s += g_deg[idx];
    }
    int lane = t & 31, wid = t >> 5;
    int v = s;
#pragma unroll
    for (int o = 1; o < 32; o <<= 1) {
        int n = __shfl_up_sync(0xffffffffu, v, o);
        if (lane >= o) v += n;
    }
    if (lane == 31) warpsum[wid] = v;
    __syncthreads();
    if (wid == 0) {
        int w = warpsum[lane];
#pragma unroll
        for (int o = 1; o < 32; o <<= 1) {
            int n = __shfl_up_sync(0xffffffffu, w, o);
            if (lane >= o) w += n;
        }
        warpsum[lane] = w;
    }
    __syncthreads();
    int run = v - s + (wid ? warpsum[wid - 1] : 0);
    if (t == 0) g_off[0] = 0;
    for (int i = 0; i < CH; i++) {
        int idx = base + i;
        if (idx < NNODE) { run += g_deg[idx]; g_off[idx + 1] = run; }
    }
}

__global__ void scatter_kernel(const int* __restrict__ src,
                               const int* __restrict__ dst,
                               const int* __restrict__ edges)
{
    int e = blockIdx.x * blockDim.x + threadIdx.x;
    if (e >= NEDGE) return;
    int d = dst[e];
    int idx = atomicAdd(&g_deg[d], -1) - 1;
    g_pe[g_off[d] + idx] = make_int2(src[e], edges[e]);
}

// ================= per-dst aggregation (fp16 gathers, rel in smem) =================
__global__ __launch_bounds__(256) void agg_kernel(const float* __restrict__ rel)
{
    __shared__ float srel[128 * DKK];   // 8 KB
    for (int i = threadIdx.x; i < 128 * DKK; i += 256) srel[i] = rel[i];
    __syncthreads();

    int node = (blockIdx.x * blockDim.x + threadIdx.x) >> 5;
    int lane = threadIdx.x & 31;
    if (node >= NNODE) return;

    const int beg = g_off[node];
    const int end = g_off[node + 1];

    const float4 q4 = *(const float4*)&g_q[(long)node * ND + lane * 4];
    float4 acc = make_float4(0.f, 0.f, 0.f, 0.f);
    float zacc = 0.f;

    const int eoff = (lane & 3) * 4;

    int i = beg;
    for (; i + 2 <= end; i += 2) {
        int2 p0 = g_pe[i];
        int2 p1 = g_pe[i + 1];
        uint2 kr0 = *(const uint2*)&g_hk[(long)p0.x * ND + lane * 4];
        uint2 kr1 = *(const uint2*)&g_hk[(long)p1.x * ND + lane * 4];
        uint2 vr0 = *(const uint2*)&g_hv[(long)p0.x * ND + lane * 4];
        uint2 vr1 = *(const uint2*)&g_hv[(long)p1.x * ND + lane * 4];
        const float4 e0 = *(const float4*)&srel[p0.y * DKK + eoff];
        const float4 e1 = *(const float4*)&srel[p1.y * DKK + eoff];

        float2 k0a = __half22float2(*(__half2*)&kr0.x);
        float2 k0b = __half22float2(*(__half2*)&kr0.y);
        float2 k1a = __half22float2(*(__half2*)&kr1.x);
        float2 k1b = __half22float2(*(__half2*)&kr1.y);

        float s0 = (k0a.x + e0.x) * q4.x + (k0a.y + e0.y) * q4.y +
                   (k0b.x + e0.z) * q4.z + (k0b.y + e0.w) * q4.w;
        float s1 = (k1a.x + e1.x) * q4.x + (k1a.y + e1.y) * q4.y +
                   (k1b.x + e1.z) * q4.z + (k1b.y + e1.w) * q4.w;
        s0 += __shfl_xor_sync(0xffffffffu, s0, 1);
        s1 += __shfl_xor_sync(0xffffffffu, s1, 1);
        s0 += __shfl_xor_sync(0xffffffffu, s0, 2);
        s1 += __shfl_xor_sync(0xffffffffu, s1, 2);

        float sc0 = __expf(fminf(fmaxf(s0 * 0.25f, -5.f), 5.f));
        float sc1 = __expf(fminf(fmaxf(s1 * 0.25f, -5.f), 5.f));

        float2 v0a = __half22float2(*(__half2*)&vr0.x);
        float2 v0b = __half22float2(*(__half2*)&vr0.y);
        float2 v1a = __half22float2(*(__half2*)&vr1.x);
        float2 v1b = __half22float2(*(__half2*)&vr1.y);

        acc.x += (v0a.x + e0.x) * sc0 + (v1a.x + e1.x) * sc1;
        acc.y += (v0a.y + e0.y) * sc0 + (v1a.y + e1.y) * sc1;
        acc.z += (v0b.x + e0.z) * sc0 + (v1b.x + e1.z) * sc1;
        acc.w += (v0b.y + e0.w) * sc0 + (v1b.y + e1.w) * sc1;
        zacc  += sc0 + sc1;
    }
    if (i < end) {
        int2 p0 = g_pe[i];
        uint2 kr0 = *(const uint2*)&g_hk[(long)p0.x * ND + lane * 4];
        uint2 vr0 = *(const uint2*)&g_hv[(long)p0.x * ND + lane * 4];
        const float4 e0 = *(const float4*)&srel[p0.y * DKK + eoff];
        float2 k0a = __half22float2(*(__half2*)&kr0.x);
        float2 k0b = __half22float2(*(__half2*)&kr0.y);
        float s0 = (k0a.x + e0.x) * q4.x + (k0a.y + e0.y) * q4.y +
                   (k0b.x + e0.z) * q4.z + (k0b.y + e0.w) * q4.w;
        s0 += __shfl_xor_sync(0xffffffffu, s0, 1);
        s0 += __shfl_xor_sync(0xffffffffu, s0, 2);
        float sc0 = __expf(fminf(fmaxf(s0 * 0.25f, -5.f), 5.f));
        float2 v0a = __half22float2(*(__half2*)&vr0.x);
        float2 v0b = __half22float2(*(__half2*)&vr0.y);
        acc.x += (v0a.x + e0.x) * sc0;
        acc.y += (v0a.y + e0.y) * sc0;
        acc.z += (v0b.x + e0.z) * sc0;
        acc.w += (v0b.y + e0.w) * sc0;
        zacc  += sc0;
    }

    float inv = 1.f / zacc;
    __half2* hp = (__half2*)&g_hwv[(long)node * ND + lane * 4];
    hp[0] = __floats2half2_rn(acc.x * inv, acc.y * inv);
    hp[1] = __floats2half2_rn(acc.z * inv, acc.w * inv);
}

// ---------------- host driver ----------------
extern "C" void kernel_launch(void* const* d_in, const int* in_sizes, int n_in,
                              void* d_out, int out_size)
{
    const float* x     = (const float*)d_in[0];
    const int*   edges = (const int*)  d_in[1];
    const int*   src   = (const int*)  d_in[2];
    const int*   dst   = (const int*)  d_in[3];
    const float* rel   = (const float*)d_in[4];
    const float* Wq    = (const float*)d_in[5];
    const float* bq    = (const float*)d_in[6];
    const float* Wk    = (const float*)d_in[7];
    const float* Wv    = (const float*)d_in[8];
    const float* Wo    = (const float*)d_in[9];
    const float* bo    = (const float*)d_in[10];
    const float* ln1g  = (const float*)d_in[11];
    const float* ln1b  = (const float*)d_in[12];
    const float* W1    = (const float*)d_in[13];
    const float* b1    = (const float*)d_in[14];
    const float* W2    = (const float*)d_in[15];
    const float* b2    = (const float*)d_in[16];
    const float* ln2g  = (const float*)d_in[17];
    const float* ln2b  = (const float*)d_in[18];

    const int M = NNODE;
    const int E = NEDGE;

    float *q, *t1, *x1;
    __half *hx, *hk, *hv, *hwv, *ht1, *hff, *hWq, *hWk, *hWv, *hWo, *hW1, *hW2;
    int* degp;
    cudaGetSymbolAddress((void**)&q,   g_q);
    cudaGetSymbolAddress((void**)&t1,  g_t1);
    cudaGetSymbolAddress((void**)&x1,  g_x1);
    cudaGetSymbolAddress((void**)&hx,  g_hx);
    cudaGetSymbolAddress((void**)&hk,  g_hk);
    cudaGetSymbolAddress((void**)&hv,  g_hv);
    cudaGetSymbolAddress((void**)&hwv, g_hwv);
    cudaGetSymbolAddress((void**)&ht1, g_ht1);
    cudaGetSymbolAddress((void**)&hff, g_hff);
    cudaGetSymbolAddress((void**)&hWq, g_hWq);
    cudaGetSymbolAddress((void**)&hWk, g_hWk);
    cudaGetSymbolAddress((void**)&hWv, g_hWv);
    cudaGetSymbolAddress((void**)&hWo, g_hWo);
    cudaGetSymbolAddress((void**)&hW1, g_hW1);
    cudaGetSymbolAddress((void**)&hW2, g_hW2);
    cudaGetSymbolAddress((void**)&degp, g_deg);

    cudaFuncSetAttribute(gemm_k<false, true>,
        cudaFuncAttributeMaxDynamicSharedMemorySize, GEMM_SMEM_BYTES);
    cudaFuncSetAttribute(gemm_k<true, false>,
        cudaFuncAttributeMaxDynamicSharedMemorySize, GEMM_SMEM_BYTES);
    cudaFuncSetAttribute(qkv_k,
        cudaFuncAttributeMaxDynamicSharedMemorySize, GEMM_SMEM_BYTES);

    const int MB = (M + 127) / 128;
    dim3 gQKV(MB, 3);
    dim3 gP(MB, 1);
    dim3 gF1(MB, FFD / 128);
    int eBlocks   = (E + 255) / 256;
    int aggBlocks = (M * 32 + 255) / 256;

    // ---- CSR build first (shifts ncu -s window toward qkv/agg) ----
    cudaMemsetAsync(degp, 0, NNODE * sizeof(int));
    hist_kernel<<<eBlocks, 256>>>(dst);
    scan_kernel<<<1, 1024>>>();
    scatter_kernel<<<eBlocks, 256>>>(src, dst, edges);

    // ---- one fused conversion launch ----
    cvt_all_kernel<<<(CVT_TOT / 4 + 255) / 256, 256>>>(x, Wq, Wk, Wv, Wo, W1, W2);

    const float* xin = x;     // fp32 residual source
    for (int li = 0; li < 2; li++) {
        float* xout = (li == 0) ? x1 : (float*)d_out;
        const __half* wWq = hWq + (long)li * ND * ND;
        const __half* wWk = hWk + (long)li * ND * ND;
        const __half* wWv = hWv + (long)li * ND * ND;
        const __half* wWo = hWo + (long)li * ND * ND;
        const __half* wW1 = hW1 + (long)li * FFD * ND;
        const __half* wW2 = hW2 + (long)li * ND * FFD;

        qkv_k<<<gQKV, 256, GEMM_SMEM_BYTES>>>(hx, wWq, wWk, wWv, bq + li * ND, q, hk, hv, M);

        agg_kernel<<<aggBlocks, 256>>>(rel);

        gemm_k<false, true><<<gP, 256, GEMM_SMEM_BYTES>>>(
            hwv, wWo, bo + li * ND, xin, ln1g + li * ND, ln1b + li * ND,
            t1, ht1, M, ND, ND);

        gemm_k<true, false><<<gF1, 256, GEMM_SMEM_BYTES>>>(
            ht1, wW1, b1 + li * FFD, nullptr, nullptr, nullptr,
            nullptr, hff, M, ND, FFD);

        gemm_k<false, true><<<gP, 256, GEMM_SMEM_BYTES>>>(
            hff, wW2, b2 + li * ND, t1, ln2g + li * ND, ln2b + li * ND,
            xout, hx, M, FFD, ND);

        xin = xout;
    }
}